// round 2
// baseline (speedup 1.0000x reference)
#include <cuda_runtime.h>
#include <cuda_bf16.h>
#include <cstdint>

#define B_ROWS 8192
#define D_INP  1024
#define D_OUTP 1024
#define N_EXP  8
#define HID    64
#define BKP    40   // padded K-stride in smem (bf16 units): 40*2=80B -> conflict-free frag loads

// ---------------- device scratch (no allocs allowed) ----------------
__device__ __align__(16) __nv_bfloat16 g_x_hi[B_ROWS * D_INP];
__device__ __align__(16) __nv_bfloat16 g_x_lo[B_ROWS * D_INP];
__device__ __align__(16) __nv_bfloat16 g_W_bf[N_EXP * D_OUTP * D_INP];
__device__ __align__(16) __nv_bfloat16 g_weff_hi[D_OUTP * D_INP];
__device__ __align__(16) __nv_bfloat16 g_weff_lo[D_OUTP * D_INP];
__device__ float g_align[N_EXP];
__device__ float g_w[N_EXP];

__device__ __forceinline__ float warp_sum(float v) {
#pragma unroll
    for (int o = 16; o > 0; o >>= 1) v += __shfl_xor_sync(0xffffffffu, v, o);
    return v;
}

__device__ __forceinline__ void mma_bf16(float* d, const uint32_t* a, const uint32_t* b) {
    asm volatile(
        "mma.sync.aligned.m16n8k16.row.col.f32.bf16.bf16.f32 "
        "{%0,%1,%2,%3}, {%4,%5,%6,%7}, {%8,%9}, {%0,%1,%2,%3};\n"
        : "+f"(d[0]), "+f"(d[1]), "+f"(d[2]), "+f"(d[3])
        : "r"(a[0]), "r"(a[1]), "r"(a[2]), "r"(a[3]), "r"(b[0]), "r"(b[1]));
}

// ---------------- kernel 1: spikes + bf16 split of x + bf16 of nano_W ----------------
__global__ void prep_kernel(const float* __restrict__ x, const float* __restrict__ nanoW,
                            const float* __restrict__ scale_weights, float* __restrict__ out_spk) {
    int i = blockIdx.x * blockDim.x + threadIdx.x;
    if (i < N_EXP) g_align[i] = 0.0f;
    const int N4 = B_ROWS * D_INP / 4;  // == N_EXP*D_OUTP*D_INP/4 too
    if (i >= N4) return;

    // softmax(scale_weights) — replicate reference fp ordering for the threshold test
    float s0 = scale_weights[0], s1 = scale_weights[1], s2 = scale_weights[2];
    float m = fmaxf(s0, fmaxf(s1, s2));
    float e0 = expf(s0 - m), e1 = expf(s1 - m), e2 = expf(s2 - m);
    float es = e0 + e1 + e2;
    float w0 = e0 / es, w1 = e1 / es, w2 = e2 / es;

    float4 v = reinterpret_cast<const float4*>(x)[i];
    float4 sp;
    {
        float vv[4] = {v.x, v.y, v.z, v.w};
        float ss[4];
#pragma unroll
        for (int c = 0; c < 4; c++) {
            float p0 = __fmul_rn(vv[c], w0);
            float p1 = __fmul_rn(vv[c], w1);
            float p2 = __fmul_rn(vv[c], w2);
            float mem = __fadd_rn(__fadd_rn(p0, p1), p2);
            ss[c] = (mem >= 0.8f) ? 1.0f : 0.0f;
        }
        sp.x = ss[0]; sp.y = ss[1]; sp.z = ss[2]; sp.w = ss[3];
    }
    reinterpret_cast<float4*>(out_spk)[i] = sp;

    int base = i * 4;
    float vv[4] = {v.x, v.y, v.z, v.w};
#pragma unroll
    for (int c = 0; c < 4; c++) {
        __nv_bfloat16 h = __float2bfloat16(vv[c]);
        g_x_hi[base + c] = h;
        g_x_lo[base + c] = __float2bfloat16(vv[c] - __bfloat162float(h));
    }
    float4 w = reinterpret_cast<const float4*>(nanoW)[i];
    float wv[4] = {w.x, w.y, w.z, w.w};
#pragma unroll
    for (int c = 0; c < 4; c++) g_W_bf[base + c] = __float2bfloat16(wv[c]);
}

// ---------------- kernel 2: router (1 warp per row) ----------------
__global__ void __launch_bounds__(256) router_kernel(
    const float* __restrict__ x, const float* __restrict__ gate_W,
    const float* __restrict__ cap_W1, const float* __restrict__ cap_b1,
    const float* __restrict__ ln_g, const float* __restrict__ ln_b,
    const float* __restrict__ cap_W2, const float* __restrict__ cap_b2,
    const float* __restrict__ temperature, float* __restrict__ out_rout) {
    __shared__ float sh[8][HID];
    __shared__ float ssc[8][N_EXP];
    int warp = threadIdx.x >> 5, lane = threadIdx.x & 31;
    int row = blockIdx.x * 8 + warp;

    // cache x row in registers (float4, lane-strided -> coalesced)
    const float4* xr = reinterpret_cast<const float4*>(x + (size_t)row * D_INP);
    float4 xv[8];
#pragma unroll
    for (int t = 0; t < 8; t++) xv[t] = xr[lane + 32 * t];

    // hidden dots: each iteration, warp streams one W1 row coalesced
#pragma unroll 4
    for (int k = 0; k < HID; k++) {
        const float4* wr = reinterpret_cast<const float4*>(cap_W1 + (size_t)k * D_INP);
        float a = 0.0f;
#pragma unroll
        for (int t = 0; t < 8; t++) {
            float4 w = wr[lane + 32 * t];
            a += xv[t].x * w.x + xv[t].y * w.y + xv[t].z * w.z + xv[t].w * w.w;
        }
        a = warp_sum(a);
        if (lane == 0) sh[warp][k] = a + cap_b1[k];
    }
#pragma unroll
    for (int k = 0; k < N_EXP; k++) {
        const float4* wr = reinterpret_cast<const float4*>(gate_W + (size_t)k * D_INP);
        float a = 0.0f;
#pragma unroll
        for (int t = 0; t < 8; t++) {
            float4 w = wr[lane + 32 * t];
            a += xv[t].x * w.x + xv[t].y * w.y + xv[t].z * w.z + xv[t].w * w.w;
        }
        a = warp_sum(a);
        if (lane == 0) ssc[warp][k] = a;
    }
    __syncwarp();

    // LayerNorm(64) + gelu(tanh) + capacity sigmoid
    float h0 = sh[warp][lane], h1 = sh[warp][lane + 32];
    float tot = warp_sum(h0 + h1);
    float mu = tot * (1.0f / 64.0f);
    float d0 = h0 - mu, d1 = h1 - mu;
    float var = warp_sum(d0 * d0 + d1 * d1) * (1.0f / 64.0f);
    float inv = rsqrtf(var + 1e-5f);
    float n0 = d0 * inv * ln_g[lane] + ln_b[lane];
    float n1 = d1 * inv * ln_g[lane + 32] + ln_b[lane + 32];
    const float kc = 0.7978845608028654f;
    float t0 = tanhf(kc * (n0 + 0.044715f * n0 * n0 * n0));
    float t1 = tanhf(kc * (n1 + 0.044715f * n1 * n1 * n1));
    float gl = 0.5f * n0 * (1.0f + t0) * cap_W2[lane] + 0.5f * n1 * (1.0f + t1) * cap_W2[lane + 32];
    float logit = warp_sum(gl) + cap_b2[0];
    float cap = 1.0f / (1.0f + expf(-logit));
    float tcl = fmaxf(temperature[0], 0.1f);

    if (lane == 0) {
        float g[N_EXP];
#pragma unroll
        for (int k = 0; k < N_EXP; k++) g[k] = (ssc[warp][k] * cap) * tcl;
        int i1 = 0; float v1 = g[0];
#pragma unroll
        for (int k = 1; k < N_EXP; k++) if (g[k] > v1) { v1 = g[k]; i1 = k; }
        int i2 = -1; float v2 = -1e30f;
#pragma unroll
        for (int k = 0; k < N_EXP; k++) if (k != i1 && g[k] > v2) { v2 = g[k]; i2 = k; }
        float denom = v1 + v2 + 1e-6f;
        float r[N_EXP];
#pragma unroll
        for (int k = 0; k < N_EXP; k++) r[k] = 0.0f;
        r[i1] = v1 / denom; r[i2] = v2 / denom;
        float4* o = reinterpret_cast<float4*>(out_rout + (size_t)row * N_EXP);
        o[0] = make_float4(r[0], r[1], r[2], r[3]);
        o[1] = make_float4(r[4], r[5], r[6], r[7]);
    }
}

// ---------------- kernel 3: align GEMM-reduce (bf16 mma, no output write) ----------------
__global__ void __launch_bounds__(256) align_gemm_kernel() {
    __shared__ __align__(16) __nv_bfloat16 sA[128 * BKP];
    __shared__ __align__(16) __nv_bfloat16 sB[128 * BKP];
    __shared__ float sred[8];
    int n = blockIdx.z;
    const __nv_bfloat16* A = g_x_hi + (size_t)blockIdx.x * 128 * D_INP;
    const __nv_bfloat16* Bm = g_W_bf + (size_t)n * D_OUTP * D_INP + (size_t)blockIdx.y * 128 * D_INP;
    int tid = threadIdx.x, wid = tid >> 5, lane = tid & 31;
    int wm = wid >> 1, wn = wid & 1;
    int gq = lane >> 2, cp = (lane & 3) << 1;

    float acc[2][8][4];
#pragma unroll
    for (int a = 0; a < 2; a++)
#pragma unroll
        for (int b = 0; b < 8; b++)
#pragma unroll
            for (int c = 0; c < 4; c++) acc[a][b][c] = 0.0f;

    for (int kb = 0; kb < D_INP; kb += 32) {
#pragma unroll
        for (int c = 0; c < 2; c++) {
            int idx = (tid << 1) + c;
            int r = idx >> 2, ch = (idx & 3) << 3;
            *reinterpret_cast<uint4*>(&sA[r * BKP + ch]) =
                *reinterpret_cast<const uint4*>(A + (size_t)r * D_INP + kb + ch);
            *reinterpret_cast<uint4*>(&sB[r * BKP + ch]) =
                *reinterpret_cast<const uint4*>(Bm + (size_t)r * D_INP + kb + ch);
        }
        __syncthreads();
#pragma unroll
        for (int ks = 0; ks < 2; ks++) {
            int k0 = ks * 16;
            uint32_t af[2][4], bf[8][2];
#pragma unroll
            for (int mf = 0; mf < 2; mf++) {
                int r0 = (wm * 32 + mf * 16 + gq) * BKP + k0 + cp;
                af[mf][0] = *reinterpret_cast<const uint32_t*>(&sA[r0]);
                af[mf][1] = *reinterpret_cast<const uint32_t*>(&sA[r0 + 8 * BKP]);
                af[mf][2] = *reinterpret_cast<const uint32_t*>(&sA[r0 + 8]);
                af[mf][3] = *reinterpret_cast<const uint32_t*>(&sA[r0 + 8 * BKP + 8]);
            }
#pragma unroll
            for (int nf = 0; nf < 8; nf++) {
                int c0 = (wn * 64 + nf * 8 + gq) * BKP + k0 + cp;
                bf[nf][0] = *reinterpret_cast<const uint32_t*>(&sB[c0]);
                bf[nf][1] = *reinterpret_cast<const uint32_t*>(&sB[c0 + 8]);
            }
#pragma unroll
            for (int mf = 0; mf < 2; mf++)
#pragma unroll
                for (int nf = 0; nf < 8; nf++) mma_bf16(acc[mf][nf], af[mf], bf[nf]);
        }
        __syncthreads();
    }
    float s = 0.0f;
#pragma unroll
    for (int a = 0; a < 2; a++)
#pragma unroll
        for (int b = 0; b < 8; b++)
#pragma unroll
            for (int c = 0; c < 4; c++) s += fabsf(acc[a][b][c]);
    s = warp_sum(s);
    if (lane == 0) sred[wid] = s;
    __syncthreads();
    if (tid == 0) {
        float t = 0.0f;
#pragma unroll
        for (int i = 0; i < 8; i++) t += sred[i];
        atomicAdd(&g_align[n], t);
    }
}

// ---------------- kernel 4: softmax over 8 align means ----------------
__global__ void softmax_kernel() {
    if (threadIdx.x == 0) {
        const float scale = 1.0f / (float)(B_ROWS * (long long)D_OUTP);
        float a[N_EXP], m = -1e30f;
#pragma unroll
        for (int i = 0; i < N_EXP; i++) { a[i] = g_align[i] * scale; m = fmaxf(m, a[i]); }
        float s = 0.0f;
#pragma unroll
        for (int i = 0; i < N_EXP; i++) { a[i] = expf(a[i] - m); s += a[i]; }
#pragma unroll
        for (int i = 0; i < N_EXP; i++) g_w[i] = a[i] / s;
    }
}

// ---------------- kernel 5: W_eff = sum_n w_n * W_n  (hi/lo bf16 split) ----------------
__global__ void weff_kernel(const float* __restrict__ nanoW) {
    int i = blockIdx.x * blockDim.x + threadIdx.x;
    const int N4 = D_OUTP * D_INP / 4;
    if (i >= N4) return;
    float w[N_EXP];
#pragma unroll
    for (int n = 0; n < N_EXP; n++) w[n] = g_w[n];
    float acc[4] = {0.f, 0.f, 0.f, 0.f};
#pragma unroll
    for (int n = 0; n < N_EXP; n++) {
        float4 v = reinterpret_cast<const float4*>(nanoW)[(size_t)n * N4 + i];
        acc[0] += w[n] * v.x; acc[1] += w[n] * v.y; acc[2] += w[n] * v.z; acc[3] += w[n] * v.w;
    }
    int base = i * 4;
#pragma unroll
    for (int c = 0; c < 4; c++) {
        __nv_bfloat16 h = __float2bfloat16(acc[c]);
        g_weff_hi[base + c] = h;
        g_weff_lo[base + c] = __float2bfloat16(acc[c] - __bfloat162float(h));
    }
}

// ---------------- kernel 6: final = x @ W_eff^T  (3-term bf16 split mma) ----------------
__global__ void __launch_bounds__(256) final_gemm_kernel(float* __restrict__ C) {
    __shared__ __align__(16) __nv_bfloat16 sAh[128 * BKP];
    __shared__ __align__(16) __nv_bfloat16 sAl[128 * BKP];
    __shared__ __align__(16) __nv_bfloat16 sBh[128 * BKP];
    __shared__ __align__(16) __nv_bfloat16 sBl[128 * BKP];
    const __nv_bfloat16* Ah = g_x_hi + (size_t)blockIdx.x * 128 * D_INP;
    const __nv_bfloat16* Al = g_x_lo + (size_t)blockIdx.x * 128 * D_INP;
    const __nv_bfloat16* Bh = g_weff_hi + (size_t)blockIdx.y * 128 * D_INP;
    const __nv_bfloat16* Bl = g_weff_lo + (size_t)blockIdx.y * 128 * D_INP;
    int tid = threadIdx.x, wid = tid >> 5, lane = tid & 31;
    int wm = wid >> 1, wn = wid & 1;
    int gq = lane >> 2, cp = (lane & 3) << 1;

    float acc[2][8][4];
#pragma unroll
    for (int a = 0; a < 2; a++)
#pragma unroll
        for (int b = 0; b < 8; b++)
#pragma unroll
            for (int c = 0; c < 4; c++) acc[a][b][c] = 0.0f;

    for (int kb = 0; kb < D_INP; kb += 32) {
#pragma unroll
        for (int c = 0; c < 2; c++) {
            int idx = (tid << 1) + c;
            int r = idx >> 2, ch = (idx & 3) << 3;
            size_t go = (size_t)r * D_INP + kb + ch;
            int so = r * BKP + ch;
            *reinterpret_cast<uint4*>(&sAh[so]) = *reinterpret_cast<const uint4*>(Ah + go);
            *reinterpret_cast<uint4*>(&sAl[so]) = *reinterpret_cast<const uint4*>(Al + go);
            *reinterpret_cast<uint4*>(&sBh[so]) = *reinterpret_cast<const uint4*>(Bh + go);
            *reinterpret_cast<uint4*>(&sBl[so]) = *reinterpret_cast<const uint4*>(Bl + go);
        }
        __syncthreads();
#pragma unroll
        for (int ks = 0; ks < 2; ks++) {
            int k0 = ks * 16;
            uint32_t ah[2][4], al[2][4], bf[8][2];
#pragma unroll
            for (int mf = 0; mf < 2; mf++) {
                int r0 = (wm * 32 + mf * 16 + gq) * BKP + k0 + cp;
                ah[mf][0] = *reinterpret_cast<const uint32_t*>(&sAh[r0]);
                ah[mf][1] = *reinterpret_cast<const uint32_t*>(&sAh[r0 + 8 * BKP]);
                ah[mf][2] = *reinterpret_cast<const uint32_t*>(&sAh[r0 + 8]);
                ah[mf][3] = *reinterpret_cast<const uint32_t*>(&sAh[r0 + 8 * BKP + 8]);
                al[mf][0] = *reinterpret_cast<const uint32_t*>(&sAl[r0]);
                al[mf][1] = *reinterpret_cast<const uint32_t*>(&sAl[r0 + 8 * BKP]);
                al[mf][2] = *reinterpret_cast<const uint32_t*>(&sAl[r0 + 8]);
                al[mf][3] = *reinterpret_cast<const uint32_t*>(&sAl[r0 + 8 * BKP + 8]);
            }
            // b = B_hi : acc += ah*bh + al*bh
#pragma unroll
            for (int nf = 0; nf < 8; nf++) {
                int c0 = (wn * 64 + nf * 8 + gq) * BKP + k0 + cp;
                bf[nf][0] = *reinterpret_cast<const uint32_t*>(&sBh[c0]);
                bf[nf][1] = *reinterpret_cast<const uint32_t*>(&sBh[c0 + 8]);
            }
#pragma unroll
            for (int mf = 0; mf < 2; mf++)
#pragma unroll
                for (int nf = 0; nf < 8; nf++) mma_bf16(acc[mf][nf], ah[mf], bf[nf]);
#pragma unroll
            for (int mf = 0; mf < 2; mf++)
#pragma unroll
                for (int nf = 0; nf < 8; nf++) mma_bf16(acc[mf][nf], al[mf], bf[nf]);
            // b = B_lo : acc += ah*bl
#pragma unroll
            for (int nf = 0; nf < 8; nf++) {
                int c0 = (wn * 64 + nf * 8 + gq) * BKP + k0 + cp;
                bf[nf][0] = *reinterpret_cast<const uint32_t*>(&sBl[c0]);
                bf[nf][1] = *reinterpret_cast<const uint32_t*>(&sBl[c0 + 8]);
            }
#pragma unroll
            for (int mf = 0; mf < 2; mf++)
#pragma unroll
                for (int nf = 0; nf < 8; nf++) mma_bf16(acc[mf][nf], ah[mf], bf[nf]);
        }
        __syncthreads();
    }
    // epilogue: write C
#pragma unroll
    for (int mf = 0; mf < 2; mf++) {
        int r0 = blockIdx.x * 128 + wm * 32 + mf * 16 + gq;
#pragma unroll
        for (int nf = 0; nf < 8; nf++) {
            int col = blockIdx.y * 128 + wn * 64 + nf * 8 + cp;
            *reinterpret_cast<float2*>(&C[(size_t)r0 * D_OUTP + col]) =
                make_float2(acc[mf][nf][0], acc[mf][nf][1]);
            *reinterpret_cast<float2*>(&C[(size_t)(r0 + 8) * D_OUTP + col]) =
                make_float2(acc[mf][nf][2], acc[mf][nf][3]);
        }
    }
}

// ---------------- launch ----------------
extern "C" void kernel_launch(void* const* d_in, const int* in_sizes, int n_in,
                              void* d_out, int out_size) {
    const float* x           = (const float*)d_in[0];
    const float* gate_W      = (const float*)d_in[1];
    const float* cap_W1      = (const float*)d_in[2];
    const float* cap_b1      = (const float*)d_in[3];
    const float* ln_g        = (const float*)d_in[4];
    const float* ln_b        = (const float*)d_in[5];
    const float* cap_W2      = (const float*)d_in[6];
    const float* cap_b2      = (const float*)d_in[7];
    const float* temperature = (const float*)d_in[8];
    const float* scale_w     = (const float*)d_in[9];
    const float* nano_W      = (const float*)d_in[10];

    float* out = (float*)d_out;
    float* out_final = out;                                   // [8192,1024]
    float* out_rout  = out + (size_t)B_ROWS * D_OUTP;         // [8192,8]
    float* out_spk   = out_rout + (size_t)B_ROWS * N_EXP;     // [8192,1024]

    prep_kernel<<<8192, 256>>>(x, nano_W, scale_w, out_spk);
    router_kernel<<<1024, 256>>>(x, gate_W, cap_W1, cap_b1, ln_g, ln_b, cap_W2, cap_b2,
                                 temperature, out_rout);
    align_gemm_kernel<<<dim3(64, 8, 8), 256>>>();
    softmax_kernel<<<1, 32>>>();
    weff_kernel<<<1024, 256>>>(nano_W);
    final_gemm_kernel<<<dim3(64, 8), 256>>>(out_final);
}

// round 3
// speedup vs baseline: 1.0013x; 1.0013x over previous
#include <cuda_runtime.h>
#include <cuda_bf16.h>
#include <cstdint>

#define B_ROWS 8192
#define D_INP  1024
#define D_OUTP 1024
#define N_EXP  8
#define HID    64
#define BKP    40   // padded K-stride in smem (bf16 units): 40*2=80B -> conflict-free frag loads

// ---------------- device scratch (no allocs allowed) ----------------
__device__ __align__(16) __nv_bfloat16 g_x_hi[B_ROWS * D_INP];
__device__ __align__(16) __nv_bfloat16 g_x_lo[B_ROWS * D_INP];
__device__ __align__(16) __nv_bfloat16 g_W_bf[N_EXP * D_OUTP * D_INP];
__device__ __align__(16) __nv_bfloat16 g_weff_hi[D_OUTP * D_INP];
__device__ __align__(16) __nv_bfloat16 g_weff_lo[D_OUTP * D_INP];
__device__ float g_align[N_EXP];
__device__ float g_w[N_EXP];

__device__ __forceinline__ float warp_sum(float v) {
#pragma unroll
    for (int o = 16; o > 0; o >>= 1) v += __shfl_xor_sync(0xffffffffu, v, o);
    return v;
}

__device__ __forceinline__ void mma_bf16(float* d, const uint32_t* a, const uint32_t* b) {
    asm volatile(
        "mma.sync.aligned.m16n8k16.row.col.f32.bf16.bf16.f32 "
        "{%0,%1,%2,%3}, {%4,%5,%6,%7}, {%8,%9}, {%0,%1,%2,%3};\n"
        : "+f"(d[0]), "+f"(d[1]), "+f"(d[2]), "+f"(d[3])
        : "r"(a[0]), "r"(a[1]), "r"(a[2]), "r"(a[3]), "r"(b[0]), "r"(b[1]));
}

// ---------------- kernel 1: spikes + bf16 split of x + bf16 of nano_W ----------------
__global__ void prep_kernel(const float* __restrict__ x, const float* __restrict__ nanoW,
                            const float* __restrict__ scale_weights, float* __restrict__ out_spk) {
    int i = blockIdx.x * blockDim.x + threadIdx.x;
    if (i < N_EXP) g_align[i] = 0.0f;
    const int N4 = B_ROWS * D_INP / 4;  // == N_EXP*D_OUTP*D_INP/4 too
    if (i >= N4) return;

    // softmax(scale_weights) — replicate reference fp ordering for the threshold test
    float s0 = scale_weights[0], s1 = scale_weights[1], s2 = scale_weights[2];
    float m = fmaxf(s0, fmaxf(s1, s2));
    float e0 = expf(s0 - m), e1 = expf(s1 - m), e2 = expf(s2 - m);
    float es = e0 + e1 + e2;
    float w0 = e0 / es, w1 = e1 / es, w2 = e2 / es;

    float4 v = reinterpret_cast<const float4*>(x)[i];
    float4 sp;
    {
        float vv[4] = {v.x, v.y, v.z, v.w};
        float ss[4];
#pragma unroll
        for (int c = 0; c < 4; c++) {
            float p0 = __fmul_rn(vv[c], w0);
            float p1 = __fmul_rn(vv[c], w1);
            float p2 = __fmul_rn(vv[c], w2);
            float mem = __fadd_rn(__fadd_rn(p0, p1), p2);
            ss[c] = (mem >= 0.8f) ? 1.0f : 0.0f;
        }
        sp.x = ss[0]; sp.y = ss[1]; sp.z = ss[2]; sp.w = ss[3];
    }
    reinterpret_cast<float4*>(out_spk)[i] = sp;

    int base = i * 4;
    float vv[4] = {v.x, v.y, v.z, v.w};
#pragma unroll
    for (int c = 0; c < 4; c++) {
        __nv_bfloat16 h = __float2bfloat16(vv[c]);
        g_x_hi[base + c] = h;
        g_x_lo[base + c] = __float2bfloat16(vv[c] - __bfloat162float(h));
    }
    float4 w = reinterpret_cast<const float4*>(nanoW)[i];
    float wv[4] = {w.x, w.y, w.z, w.w};
#pragma unroll
    for (int c = 0; c < 4; c++) g_W_bf[base + c] = __float2bfloat16(wv[c]);
}

// ---------------- kernel 2: router (1 warp per row) ----------------
__global__ void __launch_bounds__(256) router_kernel(
    const float* __restrict__ x, const float* __restrict__ gate_W,
    const float* __restrict__ cap_W1, const float* __restrict__ cap_b1,
    const float* __restrict__ ln_g, const float* __restrict__ ln_b,
    const float* __restrict__ cap_W2, const float* __restrict__ cap_b2,
    const float* __restrict__ temperature, float* __restrict__ out_rout) {
    __shared__ float sh[8][HID];
    __shared__ float ssc[8][N_EXP];
    int warp = threadIdx.x >> 5, lane = threadIdx.x & 31;
    int row = blockIdx.x * 8 + warp;

    // cache x row in registers (float4, lane-strided -> coalesced)
    const float4* xr = reinterpret_cast<const float4*>(x + (size_t)row * D_INP);
    float4 xv[8];
#pragma unroll
    for (int t = 0; t < 8; t++) xv[t] = xr[lane + 32 * t];

    // hidden dots: each iteration, warp streams one W1 row coalesced
#pragma unroll 4
    for (int k = 0; k < HID; k++) {
        const float4* wr = reinterpret_cast<const float4*>(cap_W1 + (size_t)k * D_INP);
        float a = 0.0f;
#pragma unroll
        for (int t = 0; t < 8; t++) {
            float4 w = wr[lane + 32 * t];
            a += xv[t].x * w.x + xv[t].y * w.y + xv[t].z * w.z + xv[t].w * w.w;
        }
        a = warp_sum(a);
        if (lane == 0) sh[warp][k] = a + cap_b1[k];
    }
#pragma unroll
    for (int k = 0; k < N_EXP; k++) {
        const float4* wr = reinterpret_cast<const float4*>(gate_W + (size_t)k * D_INP);
        float a = 0.0f;
#pragma unroll
        for (int t = 0; t < 8; t++) {
            float4 w = wr[lane + 32 * t];
            a += xv[t].x * w.x + xv[t].y * w.y + xv[t].z * w.z + xv[t].w * w.w;
        }
        a = warp_sum(a);
        if (lane == 0) ssc[warp][k] = a;
    }
    __syncwarp();

    // LayerNorm(64) + gelu(tanh) + capacity sigmoid
    float h0 = sh[warp][lane], h1 = sh[warp][lane + 32];
    float tot = warp_sum(h0 + h1);
    float mu = tot * (1.0f / 64.0f);
    float d0 = h0 - mu, d1 = h1 - mu;
    float var = warp_sum(d0 * d0 + d1 * d1) * (1.0f / 64.0f);
    float inv = rsqrtf(var + 1e-5f);
    float n0 = d0 * inv * ln_g[lane] + ln_b[lane];
    float n1 = d1 * inv * ln_g[lane + 32] + ln_b[lane + 32];
    const float kc = 0.7978845608028654f;
    float t0 = tanhf(kc * (n0 + 0.044715f * n0 * n0 * n0));
    float t1 = tanhf(kc * (n1 + 0.044715f * n1 * n1 * n1));
    float gl = 0.5f * n0 * (1.0f + t0) * cap_W2[lane] + 0.5f * n1 * (1.0f + t1) * cap_W2[lane + 32];
    float logit = warp_sum(gl) + cap_b2[0];
    float cap = 1.0f / (1.0f + expf(-logit));
    float tcl = fmaxf(temperature[0], 0.1f);

    if (lane == 0) {
        float g[N_EXP];
#pragma unroll
        for (int k = 0; k < N_EXP; k++) g[k] = (ssc[warp][k] * cap) * tcl;
        int i1 = 0; float v1 = g[0];
#pragma unroll
        for (int k = 1; k < N_EXP; k++) if (g[k] > v1) { v1 = g[k]; i1 = k; }
        int i2 = -1; float v2 = -1e30f;
#pragma unroll
        for (int k = 0; k < N_EXP; k++) if (k != i1 && g[k] > v2) { v2 = g[k]; i2 = k; }
        float denom = v1 + v2 + 1e-6f;
        float r[N_EXP];
#pragma unroll
        for (int k = 0; k < N_EXP; k++) r[k] = 0.0f;
        r[i1] = v1 / denom; r[i2] = v2 / denom;
        float4* o = reinterpret_cast<float4*>(out_rout + (size_t)row * N_EXP);
        o[0] = make_float4(r[0], r[1], r[2], r[3]);
        o[1] = make_float4(r[4], r[5], r[6], r[7]);
    }
}

// ---------------- kernel 3: align GEMM-reduce (bf16 mma, no output write) ----------------
__global__ void __launch_bounds__(256) align_gemm_kernel() {
    __shared__ __align__(16) __nv_bfloat16 sA[128 * BKP];
    __shared__ __align__(16) __nv_bfloat16 sB[128 * BKP];
    __shared__ float sred[8];
    int n = blockIdx.z;
    const __nv_bfloat16* A = g_x_hi + (size_t)blockIdx.x * 128 * D_INP;
    const __nv_bfloat16* Bm = g_W_bf + (size_t)n * D_OUTP * D_INP + (size_t)blockIdx.y * 128 * D_INP;
    int tid = threadIdx.x, wid = tid >> 5, lane = tid & 31;
    int wm = wid >> 1, wn = wid & 1;
    int gq = lane >> 2, cp = (lane & 3) << 1;

    float acc[2][8][4];
#pragma unroll
    for (int a = 0; a < 2; a++)
#pragma unroll
        for (int b = 0; b < 8; b++)
#pragma unroll
            for (int c = 0; c < 4; c++) acc[a][b][c] = 0.0f;

    for (int kb = 0; kb < D_INP; kb += 32) {
#pragma unroll
        for (int c = 0; c < 2; c++) {
            int idx = (tid << 1) + c;
            int r = idx >> 2, ch = (idx & 3) << 3;
            *reinterpret_cast<uint4*>(&sA[r * BKP + ch]) =
                *reinterpret_cast<const uint4*>(A + (size_t)r * D_INP + kb + ch);
            *reinterpret_cast<uint4*>(&sB[r * BKP + ch]) =
                *reinterpret_cast<const uint4*>(Bm + (size_t)r * D_INP + kb + ch);
        }
        __syncthreads();
#pragma unroll
        for (int ks = 0; ks < 2; ks++) {
            int k0 = ks * 16;
            uint32_t af[2][4], bf[8][2];
#pragma unroll
            for (int mf = 0; mf < 2; mf++) {
                int r0 = (wm * 32 + mf * 16 + gq) * BKP + k0 + cp;
                af[mf][0] = *reinterpret_cast<const uint32_t*>(&sA[r0]);
                af[mf][1] = *reinterpret_cast<const uint32_t*>(&sA[r0 + 8 * BKP]);
                af[mf][2] = *reinterpret_cast<const uint32_t*>(&sA[r0 + 8]);
                af[mf][3] = *reinterpret_cast<const uint32_t*>(&sA[r0 + 8 * BKP + 8]);
            }
#pragma unroll
            for (int nf = 0; nf < 8; nf++) {
                int c0 = (wn * 64 + nf * 8 + gq) * BKP + k0 + cp;
                bf[nf][0] = *reinterpret_cast<const uint32_t*>(&sB[c0]);
                bf[nf][1] = *reinterpret_cast<const uint32_t*>(&sB[c0 + 8]);
            }
#pragma unroll
            for (int mf = 0; mf < 2; mf++)
#pragma unroll
                for (int nf = 0; nf < 8; nf++) mma_bf16(acc[mf][nf], af[mf], bf[nf]);
        }
        __syncthreads();
    }
    float s = 0.0f;
#pragma unroll
    for (int a = 0; a < 2; a++)
#pragma unroll
        for (int b = 0; b < 8; b++)
#pragma unroll
            for (int c = 0; c < 4; c++) s += fabsf(acc[a][b][c]);
    s = warp_sum(s);
    if (lane == 0) sred[wid] = s;
    __syncthreads();
    if (tid == 0) {
        float t = 0.0f;
#pragma unroll
        for (int i = 0; i < 8; i++) t += sred[i];
        atomicAdd(&g_align[n], t);
    }
}

// ---------------- kernel 4: softmax over 8 align means ----------------
__global__ void softmax_kernel() {
    if (threadIdx.x == 0) {
        const float scale = 1.0f / (float)(B_ROWS * (long long)D_OUTP);
        float a[N_EXP], m = -1e30f;
#pragma unroll
        for (int i = 0; i < N_EXP; i++) { a[i] = g_align[i] * scale; m = fmaxf(m, a[i]); }
        float s = 0.0f;
#pragma unroll
        for (int i = 0; i < N_EXP; i++) { a[i] = expf(a[i] - m); s += a[i]; }
#pragma unroll
        for (int i = 0; i < N_EXP; i++) g_w[i] = a[i] / s;
    }
}

// ---------------- kernel 5: W_eff = sum_n w_n * W_n  (hi/lo bf16 split) ----------------
__global__ void weff_kernel(const float* __restrict__ nanoW) {
    int i = blockIdx.x * blockDim.x + threadIdx.x;
    const int N4 = D_OUTP * D_INP / 4;
    if (i >= N4) return;
    float w[N_EXP];
#pragma unroll
    for (int n = 0; n < N_EXP; n++) w[n] = g_w[n];
    float acc[4] = {0.f, 0.f, 0.f, 0.f};
#pragma unroll
    for (int n = 0; n < N_EXP; n++) {
        float4 v = reinterpret_cast<const float4*>(nanoW)[(size_t)n * N4 + i];
        acc[0] += w[n] * v.x; acc[1] += w[n] * v.y; acc[2] += w[n] * v.z; acc[3] += w[n] * v.w;
    }
    int base = i * 4;
#pragma unroll
    for (int c = 0; c < 4; c++) {
        __nv_bfloat16 h = __float2bfloat16(acc[c]);
        g_weff_hi[base + c] = h;
        g_weff_lo[base + c] = __float2bfloat16(acc[c] - __bfloat162float(h));
    }
}

// ---------------- kernel 6: final = x @ W_eff^T  (3-term bf16 split mma) ----------------
__global__ void __launch_bounds__(256) final_gemm_kernel(float* __restrict__ C) {
    __shared__ __align__(16) __nv_bfloat16 sAh[128 * BKP];
    __shared__ __align__(16) __nv_bfloat16 sAl[128 * BKP];
    __shared__ __align__(16) __nv_bfloat16 sBh[128 * BKP];
    __shared__ __align__(16) __nv_bfloat16 sBl[128 * BKP];
    const __nv_bfloat16* Ah = g_x_hi + (size_t)blockIdx.x * 128 * D_INP;
    const __nv_bfloat16* Al = g_x_lo + (size_t)blockIdx.x * 128 * D_INP;
    const __nv_bfloat16* Bh = g_weff_hi + (size_t)blockIdx.y * 128 * D_INP;
    const __nv_bfloat16* Bl = g_weff_lo + (size_t)blockIdx.y * 128 * D_INP;
    int tid = threadIdx.x, wid = tid >> 5, lane = tid & 31;
    int wm = wid >> 1, wn = wid & 1;
    int gq = lane >> 2, cp = (lane & 3) << 1;

    float acc[2][8][4];
#pragma unroll
    for (int a = 0; a < 2; a++)
#pragma unroll
        for (int b = 0; b < 8; b++)
#pragma unroll
            for (int c = 0; c < 4; c++) acc[a][b][c] = 0.0f;

    for (int kb = 0; kb < D_INP; kb += 32) {
#pragma unroll
        for (int c = 0; c < 2; c++) {
            int idx = (tid << 1) + c;
            int r = idx >> 2, ch = (idx & 3) << 3;
            size_t go = (size_t)r * D_INP + kb + ch;
            int so = r * BKP + ch;
            *reinterpret_cast<uint4*>(&sAh[so]) = *reinterpret_cast<const uint4*>(Ah + go);
            *reinterpret_cast<uint4*>(&sAl[so]) = *reinterpret_cast<const uint4*>(Al + go);
            *reinterpret_cast<uint4*>(&sBh[so]) = *reinterpret_cast<const uint4*>(Bh + go);
            *reinterpret_cast<uint4*>(&sBl[so]) = *reinterpret_cast<const uint4*>(Bl + go);
        }
        __syncthreads();
#pragma unroll
        for (int ks = 0; ks < 2; ks++) {
            int k0 = ks * 16;
            uint32_t ah[2][4], al[2][4], bf[8][2];
#pragma unroll
            for (int mf = 0; mf < 2; mf++) {
                int r0 = (wm * 32 + mf * 16 + gq) * BKP + k0 + cp;
                ah[mf][0] = *reinterpret_cast<const uint32_t*>(&sAh[r0]);
                ah[mf][1] = *reinterpret_cast<const uint32_t*>(&sAh[r0 + 8 * BKP]);
                ah[mf][2] = *reinterpret_cast<const uint32_t*>(&sAh[r0 + 8]);
                ah[mf][3] = *reinterpret_cast<const uint32_t*>(&sAh[r0 + 8 * BKP + 8]);
                al[mf][0] = *reinterpret_cast<const uint32_t*>(&sAl[r0]);
                al[mf][1] = *reinterpret_cast<const uint32_t*>(&sAl[r0 + 8 * BKP]);
                al[mf][2] = *reinterpret_cast<const uint32_t*>(&sAl[r0 + 8]);
                al[mf][3] = *reinterpret_cast<const uint32_t*>(&sAl[r0 + 8 * BKP + 8]);
            }
            // b = B_hi : acc += ah*bh + al*bh
#pragma unroll
            for (int nf = 0; nf < 8; nf++) {
                int c0 = (wn * 64 + nf * 8 + gq) * BKP + k0 + cp;
                bf[nf][0] = *reinterpret_cast<const uint32_t*>(&sBh[c0]);
                bf[nf][1] = *reinterpret_cast<const uint32_t*>(&sBh[c0 + 8]);
            }
#pragma unroll
            for (int mf = 0; mf < 2; mf++)
#pragma unroll
                for (int nf = 0; nf < 8; nf++) mma_bf16(acc[mf][nf], ah[mf], bf[nf]);
#pragma unroll
            for (int mf = 0; mf < 2; mf++)
#pragma unroll
                for (int nf = 0; nf < 8; nf++) mma_bf16(acc[mf][nf], al[mf], bf[nf]);
            // b = B_lo : acc += ah*bl
#pragma unroll
            for (int nf = 0; nf < 8; nf++) {
                int c0 = (wn * 64 + nf * 8 + gq) * BKP + k0 + cp;
                bf[nf][0] = *reinterpret_cast<const uint32_t*>(&sBl[c0]);
                bf[nf][1] = *reinterpret_cast<const uint32_t*>(&sBl[c0 + 8]);
            }
#pragma unroll
            for (int mf = 0; mf < 2; mf++)
#pragma unroll
                for (int nf = 0; nf < 8; nf++) mma_bf16(acc[mf][nf], ah[mf], bf[nf]);
        }
        __syncthreads();
    }
    // epilogue: write C
#pragma unroll
    for (int mf = 0; mf < 2; mf++) {
        int r0 = blockIdx.x * 128 + wm * 32 + mf * 16 + gq;
#pragma unroll
        for (int nf = 0; nf < 8; nf++) {
            int col = blockIdx.y * 128 + wn * 64 + nf * 8 + cp;
            *reinterpret_cast<float2*>(&C[(size_t)r0 * D_OUTP + col]) =
                make_float2(acc[mf][nf][0], acc[mf][nf][1]);
            *reinterpret_cast<float2*>(&C[(size_t)(r0 + 8) * D_OUTP + col]) =
                make_float2(acc[mf][nf][2], acc[mf][nf][3]);
        }
    }
}

// ---------------- launch ----------------
extern "C" void kernel_launch(void* const* d_in, const int* in_sizes, int n_in,
                              void* d_out, int out_size) {
    const float* x           = (const float*)d_in[0];
    const float* gate_W      = (const float*)d_in[1];
    const float* cap_W1      = (const float*)d_in[2];
    const float* cap_b1      = (const float*)d_in[3];
    const float* ln_g        = (const float*)d_in[4];
    const float* ln_b        = (const float*)d_in[5];
    const float* cap_W2      = (const float*)d_in[6];
    const float* cap_b2      = (const float*)d_in[7];
    const float* temperature = (const float*)d_in[8];
    const float* scale_w     = (const float*)d_in[9];
    const float* nano_W      = (const float*)d_in[10];

    float* out = (float*)d_out;
    float* out_final = out;                                   // [8192,1024]
    float* out_rout  = out + (size_t)B_ROWS * D_OUTP;         // [8192,8]
    float* out_spk   = out_rout + (size_t)B_ROWS * N_EXP;     // [8192,1024]

    prep_kernel<<<8192, 256>>>(x, nano_W, scale_w, out_spk);
    router_kernel<<<1024, 256>>>(x, gate_W, cap_W1, cap_b1, ln_g, ln_b, cap_W2, cap_b2,
                                 temperature, out_rout);
    align_gemm_kernel<<<dim3(64, 8, 8), 256>>>();
    softmax_kernel<<<1, 32>>>();
    weff_kernel<<<1024, 256>>>(nano_W);
    final_gemm_kernel<<<dim3(64, 8), 256>>>(out_final);
}